// round 14
// baseline (speedup 1.0000x reference)
#include <cuda_runtime.h>
#include <cstdint>
#include <cstddef>

// Problem shape (fixed by setup_inputs)
#define B_    8
#define S_    4096
#define D_    1024

// Champion tiling (R7): DT=32 lanes, 8 warps, CT=256-row chunks
#define DT    32
#define NW    8
#define CW    32
#define CT    (NW * CW)           // 256 rows per chunk
#define NTHR  256
#define NCHAIN 256                // (batch, d-tile) chains
#define TOTCH (NCHAIN * 16)       // 4096 chunk-units of 256 rows
#define NBLK  296                 // exactly 2 blocks per SM, one wave

// Cross-cut handoff: key = consumer block id. Producer bid publishes to bid+1
// iff its range ends mid-chain; consumer bid reads iff its range starts
// mid-chain (the two conditions are identical by construction). Consumer
// clears after reading -> flags return to 0 for the next graph replay.
__device__ volatile int g_sf[NBLK];
__device__ float        g_sv[NBLK][DT];

struct __align__(16) Smem {
    float  xbuf[2][CT][DT];       // 64 KB; xbuf[1] doubles as id scratch (32 KB)
    float4 tbl[2][CT];            // 8 KB  (m, n, 1/n, c) double-buffered
    float  aggL[NW][DT];          // 1 KB
    float  aggP[2][NW];
    unsigned short pos[S_];       // 8 KB absolute position-in-group
    unsigned short spanEnd[NTHR];
    unsigned short spanCarry[NTHR];
    unsigned char  spanFR[NTHR];
    int    modeAcc, frqAcc;
};                                 // ~82.5 KB -> 2 blocks/SM

__device__ __forceinline__ unsigned smem_u32(const void* p) {
    return (unsigned)__cvta_generic_to_shared(p);
}
__device__ __forceinline__ void cp16(unsigned dst, const void* src) {
    asm volatile("cp.async.cg.shared.global [%0], [%1], 16;\n" :: "r"(dst), "l"(src));
}
__device__ __forceinline__ void cp_commit() {
    asm volatile("cp.async.commit_group;\n");
}
__device__ __forceinline__ void cp_wait0() {
    asm volatile("cp.async.wait_group 0;\n" ::: "memory");
}

// Champion per-chunk table build (lane <-> timestep of warp's subchunk).
__device__ __forceinline__ void build_tbl(Smem* sm, int bb, int cc,
                                          int tid, int w, int l) {
    int p = sm->pos[cc * CT + tid];
    float pf = (float)p;
    unsigned rmask = __ballot_sync(~0u, p == 1);
    unsigned above = rmask & ~((2u << l) - 1u);
    float cf = above ? 0.0f : pf;
    sm->tbl[bb][tid] = make_float4((p != 1) ? 1.f : 0.f, pf,
                                   __fdividef(1.f, pf), cf);
    if (l == 0) sm->aggP[bb][w] = rmask ? 0.f : 1.f;
}

__global__ void __launch_bounds__(NTHR, 2)
pool_scan_kernel(const float* __restrict__ emb,
                 const int*   __restrict__ idw,   // raw 32-bit word view of ids
                 float* __restrict__ out)
{
    extern __shared__ char raw[];
    Smem* sm = reinterpret_cast<Smem*>(raw);

    const int tid = threadIdx.x;
    const int w   = tid >> 5;
    const int l   = tid & 31;
    const int bid = blockIdx.x;

    // ---- even split of 4096 chunk-units over 296 blocks ----
    const int gStart = (TOTCH * bid) / NBLK;
    const int gEnd   = (TOTCH * (bid + 1)) / NBLK;
    const int c0     = gStart >> 4;
    const int k0     = gStart & 15;
    const int endA   = min(gEnd, (c0 + 1) << 4);
    const int npiece = (gEnd > ((c0 + 1) << 4)) ? 2 : 1;

    // ---- dtype detect (globally-safe window; odd words zero iff int64) ----
    if (tid == 0) sm->modeAcc = 0;
    __syncthreads();
    {
        int acc = 0;
        #pragma unroll
        for (int k = 0; k < 8; k++)
            acc |= __ldg(&idw[2 * (tid * 8 + k) + 1]);
        #pragma unroll
        for (int o = 16; o; o >>= 1) acc |= __shfl_xor_sync(~0u, acc, o);
        if (l == 0) atomicOr(&sm->modeAcc, acc);
    }
    __syncthreads();
    const bool mode64 = (sm->modeAcc == 0);

    // saved piece-A info for the epilogue
    int   frqA = 0, posStartA = 0, rowStartA = 0, chainA = c0;
    float cnLast = 0.f;
    bool  hasResetLast = false;

    for (int pc = 0; pc < npiece; pc++) {
        const int chain = (pc == 0) ? c0 : c0 + 1;
        const int ka    = (pc == 0) ? k0 : 0;
        const int kb    = (pc == 0) ? (endA - (c0 << 4)) : (gEnd - ((c0 + 1) << 4));
        const int rowStart = ka << 8;           // piece rows [rowStart, kb*256)
        const int rowsTot  = kb << 8;           // ids needed: [0, rowsTot)

        const int b  = chain >> 5;
        const int d0 = (chain & 31) * DT;
        const float* xg = emb + ((size_t)b * S_) * D_ + d0;
        float*       og = out + ((size_t)b * S_) * D_ + d0;

        // ===== piece prologue =====
        if (tid == 0) sm->frqAcc = 1 << 30;

        // x chunk ka -> xbuf[0]
        #pragma unroll
        for (int k = 0; k < 8; k++) {
            int f = tid + k * NTHR, row = f >> 3, seg = f & 7;
            cp16(smem_u32(&sm->xbuf[0][row][seg * 4]),
                 xg + (size_t)(rowStart + row) * D_ + seg * 4);
        }
        // ids [0, rowsTot) of batch b -> xbuf[1] scratch (<= 32 KB, exact fit)
        int* scratch = (int*)&sm->xbuf[1][0][0];
        {
            const int nInt4 = mode64 ? (rowsTot >> 1) : (rowsTot >> 2);
            const int* wsrc = mode64 ? (idw + 2 * (size_t)b * S_)
                                     : (idw + (size_t)b * S_);
            for (int i4 = tid; i4 < nInt4; i4 += NTHR)
                cp16(smem_u32(scratch + i4 * 4), wsrc + i4 * 4);
        }
        cp_commit();
        cp_wait0();
        __syncthreads();

        // pos pass A: thread t scans rows [t*kb, (t+1)*kb)  (covers [0, rowsTot))
        {
            const int base = tid * kb;
            int p = 0, fr = kb, fr2 = 1 << 30;
            for (int j = 0; j < kb; j++) {
                int f;
                if (mode64) f = (scratch[2 * (base + j)] == 1) &
                                (scratch[2 * (base + j) + 1] == 0);
                else        f = (scratch[base + j] == 1);
                p = f ? 1 : p + 1;
                if (f) {
                    if (fr == kb) fr = j;
                    int r = base + j;
                    if (r >= rowStart && r < fr2) fr2 = r;
                }
                sm->pos[base + j] = (unsigned short)p;
            }
            sm->spanEnd[tid] = (unsigned short)p;
            sm->spanFR[tid]  = (unsigned char)fr;
            if (fr2 < (1 << 30)) atomicMin(&sm->frqAcc, fr2);
        }
        __syncthreads();

        // span scan (warp 0): carry entering each of 256 spans (span len = kb)
        if (tid < 32) {
            int a = 0, bb2 = 1;
            #pragma unroll
            for (int k = 0; k < 8; k++) {
                int s  = tid * 8 + k;
                int hr = (sm->spanFR[s] < kb);
                int e  = sm->spanEnd[s];
                if (hr) { a = e; bb2 = 0; } else { a += kb; }
            }
            #pragma unroll
            for (int o = 1; o < 32; o <<= 1) {
                int pa = __shfl_up_sync(~0u, a,   o);
                int pb = __shfl_up_sync(~0u, bb2, o);
                if (tid >= o) { a = a + bb2 * pa; bb2 = bb2 * pb; }
            }
            int ex = __shfl_up_sync(~0u, a, 1);
            if (tid == 0) ex = 0;
            int c = ex;
            #pragma unroll
            for (int k = 0; k < 8; k++) {
                int s = tid * 8 + k;
                sm->spanCarry[s] = (unsigned short)c;
                int hr = (sm->spanFR[s] < kb);
                c = hr ? (int)sm->spanEnd[s] : c + kb;
            }
        }
        __syncthreads();

        // pos pass B: add carry to pre-first-reset prefix of each span
        {
            const int base = tid * kb;
            int c  = sm->spanCarry[tid];
            int fr = sm->spanFR[tid];
            if (c) {
                for (int j = 0; j < kb; j++)
                    if (j < fr)
                        sm->pos[base + j] = (unsigned short)(sm->pos[base + j] + c);
            }
        }
        __syncthreads();

        const int frq = min(sm->frqAcc, rowsTot);   // first reset >= rowStart
        if (pc == 0) {
            frqA = frq; rowStartA = rowStart; chainA = chain;
            posStartA = (rowStart < rowsTot) ? (int)sm->pos[rowStart] : 1;
        }
        hasResetLast = (frq < rowsTot);

        build_tbl(sm, 0, ka, tid, w, l);
        __syncthreads();

        // ===== champion main loop over chunks [ka, kb) =====
        float cn = 0.f;
        const int tb = w * CW;

        for (int c = ka; c < kb; ++c) {
            const int cur = (c - ka) & 1, nxt = cur ^ 1;
            const bool hasNext = (c + 1 < kb);

            if (hasNext) {
                const int t0n = (c + 1) * CT;
                #pragma unroll
                for (int k = 0; k < 8; k++) {
                    int f = tid + k * NTHR, row = f >> 3, seg = f & 7;
                    cp16(smem_u32(&sm->xbuf[nxt][row][seg * 4]),
                         xg + (size_t)(t0n + row) * D_ + seg * 4);
                }
                cp_commit();
                build_tbl(sm, nxt, c + 1, tid, w, l);
            }

            // pass 1: warp-local dot product with folded coefficients
            float a0 = 0.f, a1 = 0.f, a2 = 0.f, a3 = 0.f;
            #pragma unroll
            for (int j = 0; j < CW; j += 4) {
                a0 = fmaf(sm->xbuf[cur][tb + j + 0][l], sm->tbl[cur][tb + j + 0].w, a0);
                a1 = fmaf(sm->xbuf[cur][tb + j + 1][l], sm->tbl[cur][tb + j + 1].w, a1);
                a2 = fmaf(sm->xbuf[cur][tb + j + 2][l], sm->tbl[cur][tb + j + 2].w, a2);
                a3 = fmaf(sm->xbuf[cur][tb + j + 3][l], sm->tbl[cur][tb + j + 3].w, a3);
            }
            sm->aggL[w][l] = (a0 + a1) + (a2 + a3);
            __syncthreads();

            // combine: hoisted loads, short FMA chain
            float Lq[NW], Pq[NW];
            #pragma unroll
            for (int q = 0; q < NW; ++q) {
                Lq[q] = sm->aggL[q][l];
                Pq[q] = sm->aggP[cur][q];
            }
            float S = cn, in_S = cn;
            #pragma unroll
            for (int q = 0; q < NW; ++q) {
                if (q == w) in_S = S;
                S = fmaf(S, Pq[q], Lq[q]);
            }
            cn = S;

            // pass 2: inclusive scan + write
            float Sv = in_S;
            float* ob = og + (size_t)(c * CT + tb) * D_ + l;
            #pragma unroll
            for (int j = 0; j < CW; ++j) {
                float4 t4 = sm->tbl[cur][tb + j];
                Sv = fmaf(Sv, t4.x, sm->xbuf[cur][tb + j][l] * t4.y);
                ob[(size_t)j * D_] = Sv * t4.z;
            }

            if (hasNext) cp_wait0();
            __syncthreads();
        }
        cnLast = cn;
    }

    // ===== epilogue: cut-S consume/publish + head fixup =====
    const bool needSin  = (k0 != 0);
    const bool mustPub  = ((gEnd & 15) != 0);
    float Sin = 0.f;

    if (needSin) {
        if (tid == 0) {
            while (g_sf[bid] == 0) __nanosleep(64);
        }
        __syncthreads();
        __threadfence();
        Sin = g_sv[bid][l];
        __syncthreads();
        if (tid == 0) g_sf[bid] = 0;            // clear for next replay
    }

    if (mustPub) {
        // last piece is chain-start unless the block is single-piece mid-start;
        // in the (rare) no-reset single-piece case the true S is additive in Sin.
        float S_pub = cnLast +
            ((!hasResetLast && npiece == 1 && needSin) ? Sin : 0.f);
        if (w == 0) g_sv[bid + 1][l] = S_pub;
        __threadfence();
        __syncthreads();
        if (tid == 0) g_sf[bid + 1] = 1;
    }

    if (needSin) {
        // additive fixup on piece-A rows before its first reset
        const int bA  = chainA >> 5;
        const int dA  = (chainA & 31) * DT;
        for (int r = rowStartA + w; r < frqA; r += NW) {
            float wv = __fdividef(1.0f, (float)(posStartA + (r - rowStartA)));
            float* p = out + ((size_t)(bA * S_ + r)) * D_ + dA + l;
            *p = *p + Sin * wv;
        }
    }
}

extern "C" void kernel_launch(void* const* d_in, const int* in_sizes, int n_in,
                              void* d_out, int out_size) {
    const float* emb = (const float*)d_in[0];
    const int*   idw = (const int*)d_in[1];
    float*       out = (float*)d_out;

    (void)in_sizes; (void)n_in; (void)out_size;

    cudaFuncSetAttribute(pool_scan_kernel,
                         cudaFuncAttributeMaxDynamicSharedMemorySize,
                         (int)sizeof(Smem));

    pool_scan_kernel<<<NBLK, NTHR, sizeof(Smem)>>>(emb, idw, out);
}

// round 15
// speedup vs baseline: 1.6192x; 1.6192x over previous
#include <cuda_runtime.h>
#include <cstdint>
#include <cstddef>

// Problem shape (fixed by setup_inputs)
#define B_    8
#define S_    4096
#define D_    1024

// Tiling: champion pipeline, float2 lanes
#define NQ    2                  // S-halves per chain
#define SQ    (S_ / NQ)          // 2048 rows per block
#define DT    64                 // d-cols per block (lane owns 2)
#define NW    8                  // warps
#define CW    16                 // rows per warp-subchunk
#define CT    (NW * CW)          // 128 rows per chunk (32 KB)
#define NC    (SQ / CT)          // 16 chunks per half
#define NTHR  256
#define SPAN  (SQ / NTHR)        // 8 rows per thread in pos build
#define NCHAIN (B_ * (D_ / DT))  // 128 chains
#define NBLK  (NCHAIN * NQ)      // 256 blocks, one wave at 2/SM

// Cross-half handoff (R12-validated). Zero-init at load; producer sets,
// unique consumer clears -> invariant across graph replays.
__device__ volatile int g_run[NCHAIN];   // pos[last]+1 leaving half 0
__device__ volatile int g_sf[NCHAIN];    // final S published
__device__ float2       g_sv[NCHAIN][32];

struct __align__(16) Smem {
    float  xbuf[2][CT][DT];       // 64 KB (xbuf[1] holds ids during prologue)
    float2 tmn[2][CT];            // 2 KB  (m, n)
    float  tw[2][CT];             // 1 KB  folded pass-1 coefficient
    float  tinv[2][CT];           // 1 KB  1/n
    float2 aggL[NW][32];          // 2 KB
    float  aggP[2][NW];
    unsigned short pos[SQ];       // 4 KB
    unsigned short spanEnd[NTHR];
    unsigned short spanCarry[NTHR];
    unsigned char  spanFR[NTHR];
    int    modeAcc, frqAcc, carryIn;
};                                // ~75.6 KB -> 2 blocks/SM

__device__ __forceinline__ unsigned smem_u32(const void* p) {
    return (unsigned)__cvta_generic_to_shared(p);
}
__device__ __forceinline__ void cp16(unsigned dst, const void* src) {
    asm volatile("cp.async.cg.shared.global [%0], [%1], 16;\n" :: "r"(dst), "l"(src));
}
__device__ __forceinline__ void cp_commit() {
    asm volatile("cp.async.commit_group;\n");
}
__device__ __forceinline__ void cp_wait0() {
    asm volatile("cp.async.wait_group 0;\n" ::: "memory");
}

// Table for chunk cc -> buffer bb. Rows = tid (tid < CT). Lane<->row alignment:
// one ballot yields the 16-row suffix kill (tw) and per-subchunk kill (aggP).
__device__ __forceinline__ void build_tbl(Smem* sm, int bb, int cc, int tid) {
    if (tid < CT) {
        const int l = tid & 31;
        int p = sm->pos[cc * CT + tid];
        float pf = (float)p;
        unsigned m32  = __ballot_sync(~0u, p == 1);
        unsigned half = 0xFFFFu << (l & 16);
        unsigned above = m32 & ~((2u << l) - 1u) & half;
        sm->tw[bb][tid]   = above ? 0.f : pf;
        sm->tmn[bb][tid]  = make_float2((p != 1) ? 1.f : 0.f, pf);
        sm->tinv[bb][tid] = __fdividef(1.f, pf);
        if ((l & 15) == 0)
            sm->aggP[bb][tid >> 4] = (m32 & half) ? 0.f : 1.f;
    }
}

__global__ void __launch_bounds__(NTHR, 2)
pool_scan_kernel(const float* __restrict__ emb,
                 const int*   __restrict__ idw,   // raw 32-bit word view of ids
                 float* __restrict__ out)
{
    extern __shared__ char raw[];
    Smem* sm = reinterpret_cast<Smem*>(raw);

    const int bid   = blockIdx.x;
    const int chain = bid & (NCHAIN - 1);
    const int q     = bid >> 7;                 // half (preds dispatch first)

    const int tid = threadIdx.x;
    const int w   = tid >> 5;
    const int l   = tid & 31;

    const int ndt = D_ / DT;                    // 16 d-tiles
    const int b   = chain / ndt;
    const int d0  = (chain % ndt) * DT;

    const float* xg  = emb + ((size_t)(b * S_ + q * SQ)) * D_ + d0;
    float*       og0 = out + ((size_t)(b * S_ + q * SQ)) * D_ + d0;

    // ================= prologue =================
    if (tid == 0) { sm->modeAcc = 0; sm->frqAcc = 1 << 30; sm->carryIn = 0; }

    // chunk 0 x-tile -> xbuf[0]: 128 rows x 256 B, 8 cp16/thread
    #pragma unroll
    for (int k = 0; k < 8; k++) {
        int f = tid + k * NTHR, row = f >> 4, seg = f & 15;
        cp16(smem_u32(&sm->xbuf[0][row][seg * 4]), xg + (size_t)row * D_ + seg * 4);
    }
    cp_commit();
    __syncthreads();

    // dtype detect on globally-safe window [0,4096) words: odd words are int64
    // hi-halves (all zero) iff ids are int64 with values in [0,64).
    {
        int acc = 0;
        #pragma unroll
        for (int k = 0; k < 8; k++)
            acc |= __ldg(&idw[2 * (tid * 8 + k) + 1]);
        #pragma unroll
        for (int o = 16; o; o >>= 1) acc |= __shfl_xor_sync(~0u, acc, o);
        if (l == 0) atomicOr(&sm->modeAcc, acc);
    }
    __syncthreads();
    const bool mode64 = (sm->modeAcc == 0);

    // id window for this half -> xbuf[1] scratch (<= 16 KB, fits 32 KB)
    int* scratch = (int*)&sm->xbuf[1][0][0];
    {
        const size_t eb = (size_t)b * S_ + q * SQ;
        if (mode64) {
            const int* wsrc = idw + 2 * eb;          // 4096 words
            #pragma unroll
            for (int k = 0; k < 4; k++) {
                int i4 = tid + k * NTHR;
                cp16(smem_u32(scratch + i4 * 4), wsrc + i4 * 4);
            }
        } else {
            const int* wsrc = idw + eb;              // 2048 words
            #pragma unroll
            for (int k = 0; k < 2; k++) {
                int i4 = tid + k * NTHR;
                cp16(smem_u32(scratch + i4 * 4), wsrc + i4 * 4);
            }
        }
        cp_commit();
    }
    cp_wait0();
    __syncthreads();

    // --- pos build, pass A (SPAN=8 rows/thread) ---
    {
        const int base = tid * SPAN;
        int p = 0, fr = SPAN;
        #pragma unroll
        for (int j = 0; j < SPAN; j++) {
            int f;
            if (mode64) f = (scratch[2 * (base + j)] == 1) & (scratch[2 * (base + j) + 1] == 0);
            else        f = (scratch[base + j] == 1);
            p = f ? 1 : p + 1;
            if (f && fr == SPAN) fr = j;
            sm->pos[base + j] = (unsigned short)p;
        }
        sm->spanEnd[tid] = (unsigned short)p;
        sm->spanFR[tid]  = (unsigned char)fr;
        if (fr < SPAN) atomicMin(&sm->frqAcc, base + fr);
    }
    __syncthreads();

    // --- span scan (warp 0) ---
    if (tid < 32) {
        int a = 0, bb2 = 1;
        #pragma unroll
        for (int k = 0; k < 8; k++) {
            int s  = tid * 8 + k;
            int hr = (sm->spanFR[s] < SPAN);
            int e  = sm->spanEnd[s];
            if (hr) { a = e; bb2 = 0; } else { a += SPAN; }
        }
        #pragma unroll
        for (int o = 1; o < 32; o <<= 1) {
            int pa = __shfl_up_sync(~0u, a,   o);
            int pb = __shfl_up_sync(~0u, bb2, o);
            if (tid >= o) { a = a + bb2 * pa; bb2 = bb2 * pb; }
        }
        int ex = __shfl_up_sync(~0u, a, 1);
        if (tid == 0) ex = 0;
        int c = ex;
        #pragma unroll
        for (int k = 0; k < 8; k++) {
            int s = tid * 8 + k;
            sm->spanCarry[s] = (unsigned short)c;
            int hr = (sm->spanFR[s] < SPAN);
            c = hr ? (int)sm->spanEnd[s] : c + SPAN;
        }
    }
    __syncthreads();

    // --- pass B: intra-half carries ---
    {
        const int base = tid * SPAN;
        int c  = sm->spanCarry[tid];
        int fr = sm->spanFR[tid];
        if (c) {
            #pragma unroll
            for (int j = 0; j < SPAN; j++)
                if (j < fr) sm->pos[base + j] = (unsigned short)(sm->pos[base + j] + c);
        }
    }
    __syncthreads();

    const int frq = min(sm->frqAcc, SQ);

    // --- cross-half run-length handoff (early) ---
    if (q == 0) {
        if (tid == 0) {
            __threadfence();
            g_run[chain] = (int)sm->pos[SQ - 1] + 1;
        }
    } else {
        if (tid == 0) {
            int v;
            while ((v = g_run[chain]) == 0) __nanosleep(64);
            g_run[chain] = 0;
            sm->carryIn = v - 1;
        }
        __syncthreads();
        const int carry = sm->carryIn;
        for (int t = tid; t < frq; t += NTHR)
            sm->pos[t] = (unsigned short)(sm->pos[t] + carry);
        __syncthreads();
    }

    build_tbl(sm, 0, 0, tid);
    __syncthreads();

    // ================= main loop (champion pipeline, float2 lanes) =========
    float2 cn = make_float2(0.f, 0.f);
    const int tb = w * CW;

    for (int c = 0; c < NC; ++c) {
        const int cur = c & 1, nxt = cur ^ 1;
        const bool hasNext = (c + 1 < NC);

        if (hasNext) {
            const int t0n = (c + 1) * CT;
            #pragma unroll
            for (int k = 0; k < 8; k++) {
                int f = tid + k * NTHR, row = f >> 4, seg = f & 15;
                cp16(smem_u32(&sm->xbuf[nxt][row][seg * 4]),
                     xg + (size_t)(t0n + row) * D_ + seg * 4);
            }
            cp_commit();
            build_tbl(sm, nxt, c + 1, tid);
        }

        // pass 1: subchunk dot product with folded coefficients (LDS.64 x)
        float ax = 0.f, ay = 0.f;
        #pragma unroll
        for (int j = 0; j < CW; ++j) {
            float2 x = *(const float2*)&sm->xbuf[cur][tb + j][2 * l];
            float  cf = sm->tw[cur][tb + j];
            ax = fmaf(x.x, cf, ax);
            ay = fmaf(x.y, cf, ay);
        }
        sm->aggL[w][l] = make_float2(ax, ay);
        __syncthreads();

        // combine: hoisted loads + short FMA chain (per column pair)
        float2 Lq[NW]; float Pq[NW];
        #pragma unroll
        for (int qq = 0; qq < NW; ++qq) {
            Lq[qq] = sm->aggL[qq][l];
            Pq[qq] = sm->aggP[cur][qq];
        }
        float2 S = cn, in_S = cn;
        #pragma unroll
        for (int qq = 0; qq < NW; ++qq) {
            if (qq == w) in_S = S;
            S.x = fmaf(S.x, Pq[qq], Lq[qq].x);
            S.y = fmaf(S.y, Pq[qq], Lq[qq].y);
        }
        cn = S;

        // pass 2: inclusive scan + STG.64 writes
        float2 Sv = in_S;
        float2* ob = (float2*)(og0 + (size_t)(c * CT + tb) * D_) + l;
        #pragma unroll
        for (int j = 0; j < CW; ++j) {
            float2 mn = sm->tmn[cur][tb + j];
            float  iv = sm->tinv[cur][tb + j];
            float2 x  = *(const float2*)&sm->xbuf[cur][tb + j][2 * l];
            Sv.x = fmaf(Sv.x, mn.x, x.x * mn.y);
            Sv.y = fmaf(Sv.y, mn.x, x.y * mn.y);
            ob[(size_t)j * (D_ / 2)] = make_float2(Sv.x * iv, Sv.y * iv);
        }

        if (hasNext) cp_wait0();
        __syncthreads();
    }

    // ================= epilogue: S handoff + head fixup =================
    if (q == 0) {
        if (w == 0) g_sv[chain][l] = cn;        // cn replicated across warps
        __threadfence();
        __syncthreads();
        if (tid == 0) g_sf[chain] = 1;
    } else if (frq > 0) {
        if (tid == 0) {
            while (g_sf[chain] == 0) __nanosleep(64);
            g_sf[chain] = 0;
        }
        __syncthreads();
        __threadfence();
        const float2 S_in = g_sv[chain][l];
        for (int t = w; t < frq; t += NW) {
            float wv = __fdividef(1.0f, (float)sm->pos[t]);
            float2* p = (float2*)(og0 + (size_t)t * D_) + l;
            float2 v = *p;
            v.x += S_in.x * wv;
            v.y += S_in.y * wv;
            *p = v;
        }
    } else {
        if (tid == 0) {
            while (g_sf[chain] == 0) __nanosleep(64);
            g_sf[chain] = 0;
        }
    }
}

extern "C" void kernel_launch(void* const* d_in, const int* in_sizes, int n_in,
                              void* d_out, int out_size) {
    const float* emb = (const float*)d_in[0];
    const int*   idw = (const int*)d_in[1];
    float*       out = (float*)d_out;

    (void)in_sizes; (void)n_in; (void)out_size;

    cudaFuncSetAttribute(pool_scan_kernel,
                         cudaFuncAttributeMaxDynamicSharedMemorySize,
                         (int)sizeof(Smem));

    pool_scan_kernel<<<NBLK, NTHR, sizeof(Smem)>>>(emb, idw, out);
}

// round 16
// speedup vs baseline: 1.9471x; 1.2025x over previous
#include <cuda_runtime.h>
#include <cstdint>
#include <cstddef>

// Problem shape (fixed by setup_inputs)
#define B_   8
#define S_   4096
#define D_   1024

// Champion tiling (R3)
#define DT   32              // d-lanes per block
#define NW   8               // warps per block
#define CW   32              // timesteps per warp-subchunk
#define CT   (NW * CW)       // 256 timesteps per chunk
#define NC   (S_ / CT)       // 16 chunks per chain
#define NTHR (NW * 32)       // 256 threads
#define SPAN 16              // timesteps per thread in prologue pos build

struct __align__(16) Smem {
    float  xbuf[2][CT][DT];       // 64 KB double-buffered x tile (xbuf[1] holds
                                  //       the 16 KB id window during prologue)
    float4 tbl[2][CT];            // 8 KB per-timestep (m, n, w, _), dbl-buffered
    float  aggL[NW][DT];          // 1 KB per-warp local affine sums
    float  aggP[NW];              // per-warp carry-kill factors (0 or 1)
    unsigned short pos[S_];       // 8 KB position-in-group for the whole chain
    unsigned short spanEnd[NTHR];
    unsigned short spanCarry[NTHR];
    unsigned char  spanFR[NTHR];  // first-reset offset in span (SPAN = none)
    int    modeAcc;
};

__device__ __forceinline__ unsigned smem_u32(const void* p) {
    return (unsigned)__cvta_generic_to_shared(p);
}
__device__ __forceinline__ void cp16(unsigned dst, const void* src) {
    asm volatile("cp.async.cg.shared.global [%0], [%1], 16;\n" :: "r"(dst), "l"(src));
}
__device__ __forceinline__ void cp_commit() {
    asm volatile("cp.async.commit_group;\n");
}
__device__ __forceinline__ void cp_wait0() {
    asm volatile("cp.async.wait_group 0;\n" ::: "memory");
}
__device__ __forceinline__ void cp_wait1() {
    asm volatile("cp.async.wait_group 1;\n" ::: "memory");
}

// ---------------------------------------------------------------------------
// One block owns one full chain: (batch b, 32-wide d-tile, all S).
// out[t] = S[t]*w[t],  S = S*m + x*n  (affine segmented scan).
// Depth-2 cp.async pipeline: chunk c+1 always in flight while computing c.
// ---------------------------------------------------------------------------
__global__ void __launch_bounds__(NTHR, 2)
pool_scan_kernel(const float* __restrict__ emb,
                 const int*   __restrict__ idw,   // raw 32-bit word view of ids
                 float* __restrict__ out)
{
    extern __shared__ char raw[];
    Smem* sm = reinterpret_cast<Smem*>(raw);

    const int tid = threadIdx.x;
    const int w   = tid >> 5;
    const int l   = tid & 31;

    const int ndt = D_ / DT;                    // 32 d-tiles
    const int b   = blockIdx.x / ndt;
    const int d0  = (blockIdx.x % ndt) * DT;

    const float* xg = emb + ((size_t)b * S_) * D_ + d0;
    float*       og = out + ((size_t)b * S_) * D_ + d0;

    // ================= prologue =================
    if (tid == 0) sm->modeAcc = 0;
    {
        // chunk 0 x-tile -> xbuf[0]
        #pragma unroll
        for (int k = 0; k < 8; k++) {
            int f   = tid + k * NTHR;
            int row = f >> 3, c4 = f & 7;
            cp16(smem_u32(&sm->xbuf[0][row][c4 * 4]),
                 xg + (size_t)row * D_ + c4 * 4);
        }
        // safe id window [b*S, b*S+S) words -> xbuf[1] scratch (in-bounds and
        // even-word-aligned under both dtype interpretations)
        const int* wsrc = idw + (size_t)b * S_;
        int* scratch = (int*)&sm->xbuf[1][0][0];
        #pragma unroll
        for (int k = 0; k < 4; k++) {
            int i4 = tid + k * NTHR;
            cp16(smem_u32(scratch + i4 * 4), wsrc + i4 * 4);
        }
        cp_commit();                            // group #1: chunk0 + ids
    }
    cp_wait0();
    __syncthreads();

    // dtype detect: odd words of the window are all-zero iff int64 ids
    {
        const int* scratch = (const int*)&sm->xbuf[1][0][0];
        int acc = 0;
        #pragma unroll
        for (int k = 0; k < 8; k++)
            acc |= scratch[2 * (tid + k * NTHR) + 1];
        #pragma unroll
        for (int o = 16; o; o >>= 1) acc |= __shfl_xor_sync(~0u, acc, o);
        if (l == 0) atomicOr(&sm->modeAcc, acc);
    }
    __syncthreads();
    const bool mode64 = (sm->modeAcc == 0);

    // --- pos build, pass A: each thread scans SPAN consecutive timesteps ---
    {
        const int base = tid * SPAN;
        int p = 0, fr = SPAN;
        if (mode64) {
            const int2* q = ((const int2*)idw) + (size_t)b * S_ + base;
            #pragma unroll
            for (int j = 0; j < SPAN; j++) {
                int2 v = __ldg(&q[j]);
                int f = (v.x == 1) & (v.y == 0);
                p = f ? 1 : p + 1;
                if (f && fr == SPAN) fr = j;
                sm->pos[base + j] = (unsigned short)p;
            }
        } else {
            const int* sc = (const int*)&sm->xbuf[1][0][0];
            #pragma unroll
            for (int j = 0; j < SPAN; j++) {
                int f = (sc[base + j] == 1);
                p = f ? 1 : p + 1;
                if (f && fr == SPAN) fr = j;
                sm->pos[base + j] = (unsigned short)p;
            }
        }
        sm->spanEnd[tid] = (unsigned short)p;
        sm->spanFR[tid]  = (unsigned char)fr;
    }
    __syncthreads();   // pass A done -> id scratch (xbuf[1]) is now free

    // overlap: issue chunk 1 into xbuf[1] while span scan / pass B run
    {
        #pragma unroll
        for (int k = 0; k < 8; k++) {
            int f   = tid + k * NTHR;
            int row = f >> 3, c4 = f & 7;
            cp16(smem_u32(&sm->xbuf[1][row][c4 * 4]),
                 xg + (size_t)(CT + row) * D_ + c4 * 4);
        }
        cp_commit();                            // group #2: chunk1
    }

    // --- span scan (warp 0): carry = run length entering each span ---
    if (tid < 32) {
        int a = 0, bb = 1;
        #pragma unroll
        for (int k = 0; k < 8; k++) {
            int s  = tid * 8 + k;
            int hr = (sm->spanFR[s] < SPAN);
            int e  = sm->spanEnd[s];
            if (hr) { a = e; bb = 0; } else { a += SPAN; }
        }
        #pragma unroll
        for (int o = 1; o < 32; o <<= 1) {
            int pa = __shfl_up_sync(~0u, a,  o);
            int pb = __shfl_up_sync(~0u, bb, o);
            if (tid >= o) { a = a + bb * pa; bb = bb * pb; }
        }
        int ex = __shfl_up_sync(~0u, a, 1);
        if (tid == 0) ex = 0;
        int c = ex;
        #pragma unroll
        for (int k = 0; k < 8; k++) {
            int s = tid * 8 + k;
            sm->spanCarry[s] = (unsigned short)c;
            int hr = (sm->spanFR[s] < SPAN);
            c = hr ? (int)sm->spanEnd[s] : c + SPAN;
        }
    }
    __syncthreads();

    // --- pos build, pass B: add incoming carry to pre-first-reset prefix ---
    {
        const int base = tid * SPAN;
        int c  = sm->spanCarry[tid];
        int fr = sm->spanFR[tid];
        if (c) {
            #pragma unroll
            for (int j = 0; j < SPAN; j++)
                if (j < fr) sm->pos[base + j] = (unsigned short)(sm->pos[base + j] + c);
        }
    }
    __syncthreads();

    // --- tables for chunk 0 and chunk 1 ---
    {
        int p0 = sm->pos[tid];
        float pf0 = (float)p0;
        sm->tbl[0][tid] = make_float4(p0 != 1 ? 1.0f : 0.0f, pf0,
                                      __fdividef(1.0f, pf0), 0.0f);
        int p1 = sm->pos[CT + tid];
        float pf1 = (float)p1;
        sm->tbl[1][tid] = make_float4(p1 != 1 ? 1.0f : 0.0f, pf1,
                                      __fdividef(1.0f, pf1), 0.0f);
    }
    __syncthreads();

    // ================= main loop (depth-2 pipeline) =================
    // Invariant entering iter c: xbuf[cur]=chunk c (group retired by wait1),
    // xbuf[nxt]=chunk c+1 (in flight or done), tbl[cur]/tbl[nxt] valid.
    float cn = 0.f;                             // chain carry (affine sum)
    const int tb = w * CW;                      // warp's subchunk base in chunk

    for (int c = 0; c < NC; ++c) {
        const int cur = c & 1;

        cp_wait1();          // chunk c's group complete (c+1 may be in flight)
        __syncthreads();     // deposits visible; prior tail writes ordered

        // ---- pass 1: warp-local affine sum (from S=0) ----
        float L = 0.f;
        #pragma unroll
        for (int j = 0; j < CW; ++j) {
            float x = sm->xbuf[cur][tb + j][l];
            float2 mn = *(const float2*)&sm->tbl[cur][tb + j];
            L = fmaf(L, mn.x, x * mn.y);
        }
        {
            int pl = sm->pos[c * CT + tb + l];
            unsigned msk = __ballot_sync(~0u, pl == 1);
            if (l == 0) sm->aggP[w] = msk ? 0.f : 1.f;
        }
        sm->aggL[w][l] = L;
        __syncthreads();

        // ---- combine: exclusive prefix for this warp + new chain carry ----
        float S = cn, in_S = cn;
        #pragma unroll
        for (int q = 0; q < NW; ++q) {
            if (q == w) in_S = S;
            S = fmaf(S, sm->aggP[q], sm->aggL[q][l]);
        }
        cn = S;

        // ---- pass 2: inclusive scan + write ----
        float Sv = in_S;
        float* ob = og + (size_t)(c * CT + tb) * D_ + l;
        #pragma unroll
        for (int j = 0; j < CW; ++j) {
            float x  = sm->xbuf[cur][tb + j][l];
            float4 t4 = sm->tbl[cur][tb + j];
            Sv = fmaf(Sv, t4.x, x * t4.y);
            ob[(size_t)j * D_] = Sv * t4.z;
        }

        __syncthreads();     // all warps done reading xbuf[cur]/tbl[cur]

        // ---- tail: refill cur's buffer with chunk c+2 ----
        if (c + 2 < NC) {
            const int t0n = (c + 2) * CT;
            #pragma unroll
            for (int k = 0; k < 8; k++) {
                int f   = tid + k * NTHR;
                int row = f >> 3, c4 = f & 7;
                cp16(smem_u32(&sm->xbuf[cur][row][c4 * 4]),
                     xg + (size_t)(t0n + row) * D_ + c4 * 4);
            }
            int p = sm->pos[t0n + tid];
            float pf = (float)p;
            sm->tbl[cur][tid] = make_float4(p != 1 ? 1.0f : 0.0f, pf,
                                            __fdividef(1.0f, pf), 0.0f);
        }
        cp_commit();         // one group per iteration (empty near the tail)
    }
}

extern "C" void kernel_launch(void* const* d_in, const int* in_sizes, int n_in,
                              void* d_out, int out_size) {
    const float* emb = (const float*)d_in[0];
    const int*   idw = (const int*)d_in[1];
    float*       out = (float*)d_out;

    (void)in_sizes; (void)n_in; (void)out_size;

    cudaFuncSetAttribute(pool_scan_kernel,
                         cudaFuncAttributeMaxDynamicSharedMemorySize,
                         (int)sizeof(Smem));

    dim3 grid(B_ * (D_ / DT));   // 256 blocks, each owns a full (b, d-tile) chain
    pool_scan_kernel<<<grid, NTHR, sizeof(Smem)>>>(emb, idw, out);
}